// round 1
// baseline (speedup 1.0000x reference)
#include <cuda_runtime.h>

// Problem constants (fixed by the dataset)
#define B_   16
#define MC   2048
#define MT   4096
#define E_   512
#define NHOP 2

#define NROW_H (B_ * MC)   // 32768
#define NROW_R (B_ * MT)   // 65536

// ---------------- scratch (static device globals; no allocation allowed) ---
__device__ float g_h  [NROW_H * E_];
__device__ float g_h2 [NROW_H * E_];
__device__ float g_upd[NROW_H * E_];
__device__ float g_r  [NROW_R * E_];
__device__ float g_r2 [NROW_R * E_];
__device__ float g_cnt[NROW_H];

// ---------------- gather: out[row] = table[ids[row]] ------------------------
__global__ void gather_rows(const float* __restrict__ table,
                            const int* __restrict__ ids,
                            float* __restrict__ out) {
    const int row = blockIdx.x;
    const int id  = ids[row];
    const float4* src = (const float4*)(table + (size_t)id * E_);
    float4*       dst = (float4*)(out + (size_t)row * E_);
    dst[threadIdx.x] = src[threadIdx.x];          // 128 threads * float4 = 512 f
}

// ---------------- scatter messages + degree counts --------------------------
__global__ void scatter_upd(const int* __restrict__ head,
                            const int* __restrict__ tail,
                            const int* __restrict__ labels,
                            const float* __restrict__ h,
                            const float* __restrict__ r,
                            float* __restrict__ upd,
                            float* __restrict__ cnt) {
    const int t = blockIdx.x;                      // global triple id (b*MT + mt)
    if (labels[t] == -1) return;
    const int b  = t / MT;
    const int hi = head[t];
    const int ti = tail[t];

    const size_t rowh = (size_t)b * MC + hi;
    const size_t rowt = (size_t)b * MC + ti;

    const float4* hh = (const float4*)(h + rowh * E_);
    const float4* ht = (const float4*)(h + rowt * E_);
    const float4* rr = (const float4*)(r + (size_t)t * E_);
    float* ut = upd + rowt * E_;
    float* uh = upd + rowh * E_;

    const int i = threadIdx.x;                     // 0..127
    float4 hv = hh[i];
    float4 tv = ht[i];
    float4 rv = rr[i];
    const int o = 4 * i;
    // messages head->tail and tail->head
    atomicAdd(ut + o + 0, hv.x - rv.x);
    atomicAdd(ut + o + 1, hv.y - rv.y);
    atomicAdd(ut + o + 2, hv.z - rv.z);
    atomicAdd(ut + o + 3, hv.w - rv.w);
    atomicAdd(uh + o + 0, tv.x - rv.x);
    atomicAdd(uh + o + 1, tv.y - rv.y);
    atomicAdd(uh + o + 2, tv.z - rv.z);
    atomicAdd(uh + o + 3, tv.w - rv.w);
    if (i == 0) {
        atomicAdd(cnt + rowt, 1.0f);
        atomicAdd(cnt + rowh, 1.0f);
    }
}

// ---------------- divide upd rows by clip(count, 1) -------------------------
__global__ void scale_upd(float* __restrict__ upd, const float* __restrict__ cnt) {
    const int row = blockIdx.x;
    const float s = 1.0f / fmaxf(cnt[row], 1.0f);
    float4* u = (float4*)(upd + (size_t)row * E_);
    float4 v = u[threadIdx.x];
    v.x *= s; v.y *= s; v.z *= s; v.w *= s;
    u[threadIdx.x] = v;
}

// ---------------- SGEMM NT: C[m,n] = sum_src sum_k A_src[m,k]*W_src[n,k] ----
// N == E_ == 512, K per source == 512. 128x128x8 tile, 256 thr, 8x8 microtile.
template<int NSRC, bool RELU>
__global__ __launch_bounds__(256, 2)
void sgemm_nt(const float* __restrict__ A0, const float* __restrict__ W0,
              const float* __restrict__ A1, const float* __restrict__ W1,
              float* __restrict__ C) {
    constexpr int BM = 128, BN = 128, BK = 8;
    __shared__ float As[BK][BM + 4];
    __shared__ float Ws[BK][BN + 4];

    const int bm  = blockIdx.y * BM;
    const int bn  = blockIdx.x * BN;
    const int tid = threadIdx.x;

    const int lrow = tid >> 1;          // 0..127 : tile row being loaded
    const int lcol = (tid & 1) * 4;     // 0 or 4 : k-offset within BK

    const int ty8 = (tid >> 4) * 8;     // 0..120 : micro-tile row
    const int tx8 = (tid & 15) * 8;     // 0..120 : micro-tile col

    float acc[8][8];
    #pragma unroll
    for (int i = 0; i < 8; ++i)
        #pragma unroll
        for (int j = 0; j < 8; ++j) acc[i][j] = 0.0f;

    #pragma unroll
    for (int src = 0; src < NSRC; ++src) {
        const float* A = (src == 0) ? A0 : A1;
        const float* W = (src == 0) ? W0 : W1;

        for (int k0 = 0; k0 < E_; k0 += BK) {
            float4 av = *(const float4*)(A + (size_t)(bm + lrow) * E_ + k0 + lcol);
            float4 wv = *(const float4*)(W + (size_t)(bn + lrow) * E_ + k0 + lcol);
            __syncthreads();            // previous tile fully consumed
            As[lcol + 0][lrow] = av.x;
            As[lcol + 1][lrow] = av.y;
            As[lcol + 2][lrow] = av.z;
            As[lcol + 3][lrow] = av.w;
            Ws[lcol + 0][lrow] = wv.x;
            Ws[lcol + 1][lrow] = wv.y;
            Ws[lcol + 2][lrow] = wv.z;
            Ws[lcol + 3][lrow] = wv.w;
            __syncthreads();

            #pragma unroll
            for (int k = 0; k < BK; ++k) {
                float4 a0 = *(const float4*)&As[k][ty8];
                float4 a1 = *(const float4*)&As[k][ty8 + 4];
                float4 w0 = *(const float4*)&Ws[k][tx8];
                float4 w1 = *(const float4*)&Ws[k][tx8 + 4];
                float ar[8] = {a0.x, a0.y, a0.z, a0.w, a1.x, a1.y, a1.z, a1.w};
                float wr[8] = {w0.x, w0.y, w0.z, w0.w, w1.x, w1.y, w1.z, w1.w};
                #pragma unroll
                for (int i = 0; i < 8; ++i)
                    #pragma unroll
                    for (int j = 0; j < 8; ++j)
                        acc[i][j] = fmaf(ar[i], wr[j], acc[i][j]);
            }
        }
    }

    // epilogue
    #pragma unroll
    for (int i = 0; i < 8; ++i) {
        float* crow = C + (size_t)(bm + ty8 + i) * E_ + bn + tx8;
        float4 v0 = make_float4(acc[i][0], acc[i][1], acc[i][2], acc[i][3]);
        float4 v1 = make_float4(acc[i][4], acc[i][5], acc[i][6], acc[i][7]);
        if (RELU) {
            v0.x = fmaxf(v0.x, 0.f); v0.y = fmaxf(v0.y, 0.f);
            v0.z = fmaxf(v0.z, 0.f); v0.w = fmaxf(v0.w, 0.f);
            v1.x = fmaxf(v1.x, 0.f); v1.y = fmaxf(v1.y, 0.f);
            v1.z = fmaxf(v1.z, 0.f); v1.w = fmaxf(v1.w, 0.f);
        }
        *(float4*)(crow + 0) = v0;
        *(float4*)(crow + 4) = v1;
    }
}

// ---------------- final concat: out[t] = [h[head], r, h[tail]] --------------
__global__ void final_gather(const float* __restrict__ h,
                             const float* __restrict__ r,
                             const int* __restrict__ head,
                             const int* __restrict__ tail,
                             float* __restrict__ out) {
    const int t = blockIdx.x;
    const int b = t / MT;
    const float4* hh = (const float4*)(h + ((size_t)b * MC + head[t]) * E_);
    const float4* ht = (const float4*)(h + ((size_t)b * MC + tail[t]) * E_);
    const float4* rr = (const float4*)(r + (size_t)t * E_);
    float4* o = (float4*)(out + (size_t)t * 3 * E_);
    const int i = threadIdx.x;     // 0..127
    o[i]       = hh[i];
    o[128 + i] = rr[i];
    o[256 + i] = ht[i];
}

// ---------------- host launch ------------------------------------------------
extern "C" void kernel_launch(void* const* d_in, const int* in_sizes, int n_in,
                              void* d_out, int out_size) {
    const float* concept_table  = (const float*)d_in[0];
    const float* relation_table = (const float*)d_in[1];
    const float* W_s            = (const float*)d_in[2];
    const float* W_n            = (const float*)d_in[3];
    const float* W_r            = (const float*)d_in[4];
    const int*   concept_ids    = (const int*)d_in[5];
    const int*   relation_ids   = (const int*)d_in[6];
    const int*   head_idx       = (const int*)d_in[7];
    const int*   tail_idx       = (const int*)d_in[8];
    const int*   labels         = (const int*)d_in[9];
    float*       out            = (float*)d_out;

    float *h, *h2, *r, *r2, *upd, *cnt;
    cudaGetSymbolAddress((void**)&h,   g_h);
    cudaGetSymbolAddress((void**)&h2,  g_h2);
    cudaGetSymbolAddress((void**)&r,   g_r);
    cudaGetSymbolAddress((void**)&r2,  g_r2);
    cudaGetSymbolAddress((void**)&upd, g_upd);
    cudaGetSymbolAddress((void**)&cnt, g_cnt);

    gather_rows<<<NROW_H, 128>>>(concept_table, concept_ids, h);
    gather_rows<<<NROW_R, 128>>>(relation_table, relation_ids, r);

    float* hc = h;  float* hn = h2;
    float* rc = r;  float* rn = r2;

    for (int l = 0; l < NHOP; ++l) {
        cudaMemsetAsync(upd, 0, sizeof(float) * (size_t)NROW_H * E_);
        cudaMemsetAsync(cnt, 0, sizeof(float) * (size_t)NROW_H);

        scatter_upd<<<NROW_R, 128>>>(head_idx, tail_idx, labels, hc, rc, upd, cnt);
        scale_upd<<<NROW_H, 128>>>(upd, cnt);

        const float* Ws = W_s + (size_t)l * E_ * E_;
        const float* Wn = W_n + (size_t)l * E_ * E_;
        const float* Wr = W_r + (size_t)l * E_ * E_;

        dim3 gh(E_ / 128, NROW_H / 128);           // (4, 256)
        sgemm_nt<2, true><<<gh, 256>>>(hc, Ws, upd, Wn, hn);

        dim3 gr(E_ / 128, NROW_R / 128);           // (4, 512)
        sgemm_nt<1, false><<<gr, 256>>>(rc, Wr, (const float*)nullptr,
                                        (const float*)nullptr, rn);

        float* tmp;
        tmp = hc; hc = hn; hn = tmp;
        tmp = rc; rc = rn; rn = tmp;
    }

    final_gather<<<NROW_R, 128>>>(hc, rc, head_idx, tail_idx, out);
}

// round 2
// speedup vs baseline: 1.7990x; 1.7990x over previous
#include <cuda_runtime.h>
#include <cstdint>

// Problem constants (fixed by the dataset)
#define B_   16
#define MC   2048
#define MT   4096
#define E_   512
#define NHOP 2

#define NROW_H (B_ * MC)   // 32768
#define NROW_R (B_ * MT)   // 65536

// ---------------- scratch (static device globals; no allocation allowed) ---
__device__ float g_h  [NROW_H * E_];
__device__ float g_h2 [NROW_H * E_];
__device__ float g_upd[NROW_H * E_];
__device__ float g_r  [NROW_R * E_];
__device__ float g_r2 [NROW_R * E_];
__device__ float g_cnt[NROW_H];

// ---------------- gather: out[row] = table[ids[row]] ------------------------
__global__ void gather_rows(const float* __restrict__ table,
                            const int* __restrict__ ids,
                            float* __restrict__ out) {
    const int row = blockIdx.x;
    const int id  = ids[row];
    const float4* src = (const float4*)(table + (size_t)id * E_);
    float4*       dst = (float4*)(out + (size_t)row * E_);
    dst[threadIdx.x] = src[threadIdx.x];          // 128 threads * float4 = 512 f
}

// ---------------- scatter messages + degree counts --------------------------
__global__ void scatter_upd(const int* __restrict__ head,
                            const int* __restrict__ tail,
                            const int* __restrict__ labels,
                            const float* __restrict__ h,
                            const float* __restrict__ r,
                            float* __restrict__ upd,
                            float* __restrict__ cnt) {
    const int t = blockIdx.x;                      // global triple id (b*MT + mt)
    if (labels[t] == -1) return;
    const int b  = t / MT;
    const int hi = head[t];
    const int ti = tail[t];

    const size_t rowh = (size_t)b * MC + hi;
    const size_t rowt = (size_t)b * MC + ti;

    const float4* hh = (const float4*)(h + rowh * E_);
    const float4* ht = (const float4*)(h + rowt * E_);
    const float4* rr = (const float4*)(r + (size_t)t * E_);
    float* ut = upd + rowt * E_;
    float* uh = upd + rowh * E_;

    const int i = threadIdx.x;                     // 0..127
    float4 hv = hh[i];
    float4 tv = ht[i];
    float4 rv = rr[i];
    const int o = 4 * i;
    atomicAdd(ut + o + 0, hv.x - rv.x);
    atomicAdd(ut + o + 1, hv.y - rv.y);
    atomicAdd(ut + o + 2, hv.z - rv.z);
    atomicAdd(ut + o + 3, hv.w - rv.w);
    atomicAdd(uh + o + 0, tv.x - rv.x);
    atomicAdd(uh + o + 1, tv.y - rv.y);
    atomicAdd(uh + o + 2, tv.z - rv.z);
    atomicAdd(uh + o + 3, tv.w - rv.w);
    if (i == 0) {
        atomicAdd(cnt + rowt, 1.0f);
        atomicAdd(cnt + rowh, 1.0f);
    }
}

// ---------------- divide upd rows by clip(count, 1) -------------------------
__global__ void scale_upd(float* __restrict__ upd, const float* __restrict__ cnt) {
    const int row = blockIdx.x;
    const float s = 1.0f / fmaxf(cnt[row], 1.0f);
    float4* u = (float4*)(upd + (size_t)row * E_);
    float4 v = u[threadIdx.x];
    v.x *= s; v.y *= s; v.z *= s; v.w *= s;
    u[threadIdx.x] = v;
}

// ---------------- tf32 helpers ----------------------------------------------
__device__ __forceinline__ uint32_t f2tf32(float x) {
    uint32_t r;
    asm volatile("cvt.rna.tf32.f32 %0, %1;" : "=r"(r) : "f"(x));
    return r;
}

__device__ __forceinline__ void mma_tf32(float* c, const uint32_t* a, const uint32_t* b) {
    asm volatile(
        "mma.sync.aligned.m16n8k8.row.col.f32.tf32.tf32.f32 "
        "{%0,%1,%2,%3}, {%4,%5,%6,%7}, {%8,%9}, {%0,%1,%2,%3};\n"
        : "+f"(c[0]), "+f"(c[1]), "+f"(c[2]), "+f"(c[3])
        : "r"(a[0]), "r"(a[1]), "r"(a[2]), "r"(a[3]), "r"(b[0]), "r"(b[1]));
}

// ---------------- tf32 tensor-core GEMM NT ----------------------------------
// C[m,n] = sum_src sum_k A_src[m,k] * W_src[n,k],  K = 512 per source.
// CTA tile 128x128, BK=16, double buffered. 4 warps, each 64x64.
// Shared memory holds tiles in *fragment order* so both STS and LDS are
// conflict-free vector ops:
//   A slot: [(mf*2+ks)*32 + lane] -> 4 regs (LDS.128 per fragment)
//   B slot: [(nf*2+ks)*32 + lane] -> 2 regs (LDS.64  per fragment)
template<int NSRC, bool RELU>
__global__ __launch_bounds__(128, 2)
void gemm_tf32(const float* __restrict__ A0, const float* __restrict__ W0,
               const float* __restrict__ A1, const float* __restrict__ W1,
               float* __restrict__ C) {
    constexpr int LD = E_;
    constexpr int TOTAL = NSRC * (E_ / 16);   // 16-wide K tiles

    __shared__ uint32_t Asm[2][2048];         // 8 KB per buffer
    __shared__ uint32_t Bsm[2][2048];

    const int tid  = threadIdx.x;
    const int lane = tid & 31;
    const int wq   = tid >> 5;                // warp 0..3
    const int wm   = (wq >> 1) * 64;          // warp row base within tile
    const int wn   = (wq & 1) * 64;           // warp col base within tile
    const int bm   = blockIdx.y * 128;
    const int bn   = blockIdx.x * 128;

    // ---- loader slot geometry (constant per thread) ----
    // A: 16 blocks (mf*2+ks), thread covers blk = (tid>>5)+4*i, i=0..3
    // B: 32 blocks (nf*2+ks), thread covers blk = (tid>>5)+4*j, j=0..7
    int aoff[4];
    #pragma unroll
    for (int i = 0; i < 4; ++i) {
        int blk = (tid >> 5) + 4 * i;
        int m = (blk >> 1) * 16 + (lane >> 2);
        int k = (blk & 1) * 8 + (lane & 3);
        aoff[i] = m * LD + k;
    }
    int boff[8];
    #pragma unroll
    for (int j = 0; j < 8; ++j) {
        int blk = (tid >> 5) + 4 * j;
        int n = (blk >> 1) * 8 + (lane >> 2);
        int k = (blk & 1) * 8 + (lane & 3);
        boff[j] = n * LD + k;
    }

    float la[4][4];   // staged A values (m,k),(m+8,k),(m,k+4),(m+8,k+4)
    float lb[8][2];   // staged B values (n,k),(n,k+4)

    float acc[4][8][4];
    #pragma unroll
    for (int f = 0; f < 4; ++f)
        #pragma unroll
        for (int g = 0; g < 8; ++g)
            #pragma unroll
            for (int e = 0; e < 4; ++e) acc[f][g][e] = 0.0f;

    auto ldg_tile = [&](int t) {
        const float* A = (NSRC == 2 && t >= 32) ? A1 : A0;
        const float* W = (NSRC == 2 && t >= 32) ? W1 : W0;
        const int kg = (t & 31) * 16;
        const float* Ab = A + (size_t)bm * LD + kg;
        const float* Wb = W + (size_t)bn * LD + kg;
        #pragma unroll
        for (int i = 0; i < 4; ++i) {
            la[i][0] = Ab[aoff[i]];
            la[i][1] = Ab[aoff[i] + 8 * LD];
            la[i][2] = Ab[aoff[i] + 4];
            la[i][3] = Ab[aoff[i] + 8 * LD + 4];
        }
        #pragma unroll
        for (int j = 0; j < 8; ++j) {
            lb[j][0] = Wb[boff[j]];
            lb[j][1] = Wb[boff[j] + 4];
        }
    };

    auto sts_tile = [&](int buf) {
        #pragma unroll
        for (int i = 0; i < 4; ++i) {
            int blk = (tid >> 5) + 4 * i;
            uint4 v;
            v.x = f2tf32(la[i][0]);
            v.y = f2tf32(la[i][1]);
            v.z = f2tf32(la[i][2]);
            v.w = f2tf32(la[i][3]);
            *(uint4*)&Asm[buf][(blk * 32 + lane) * 4] = v;
        }
        #pragma unroll
        for (int j = 0; j < 8; ++j) {
            int blk = (tid >> 5) + 4 * j;
            uint2 v;
            v.x = f2tf32(lb[j][0]);
            v.y = f2tf32(lb[j][1]);
            *(uint2*)&Bsm[buf][(blk * 32 + lane) * 2] = v;
        }
    };

    auto compute = [&](int buf) {
        #pragma unroll
        for (int ks = 0; ks < 2; ++ks) {
            uint4 afr[4];
            #pragma unroll
            for (int f = 0; f < 4; ++f)
                afr[f] = *(const uint4*)&Asm[buf][(((wm >> 4) + f) * 2 + ks) * 128 + lane * 4];
            uint2 bfr[8];
            #pragma unroll
            for (int g = 0; g < 8; ++g)
                bfr[g] = *(const uint2*)&Bsm[buf][(((wn >> 3) + g) * 2 + ks) * 64 + lane * 2];
            #pragma unroll
            for (int f = 0; f < 4; ++f)
                #pragma unroll
                for (int g = 0; g < 8; ++g)
                    mma_tf32(acc[f][g], (const uint32_t*)&afr[f], (const uint32_t*)&bfr[g]);
        }
    };

    // ---- pipeline ----
    ldg_tile(0);
    sts_tile(0);
    __syncthreads();
    for (int t = 0; t < TOTAL; ++t) {
        const int buf = t & 1;
        if (t + 1 < TOTAL) ldg_tile(t + 1);
        compute(buf);
        if (t + 1 < TOTAL) {
            sts_tile(buf ^ 1);
            __syncthreads();
        }
    }

    // ---- epilogue ----
    #pragma unroll
    for (int f = 0; f < 4; ++f) {
        #pragma unroll
        for (int g = 0; g < 8; ++g) {
            const int row0 = bm + wm + f * 16 + (lane >> 2);
            const int col  = bn + wn + g * 8 + (lane & 3) * 2;
            float2 v0 = make_float2(acc[f][g][0], acc[f][g][1]);
            float2 v1 = make_float2(acc[f][g][2], acc[f][g][3]);
            if (RELU) {
                v0.x = fmaxf(v0.x, 0.f); v0.y = fmaxf(v0.y, 0.f);
                v1.x = fmaxf(v1.x, 0.f); v1.y = fmaxf(v1.y, 0.f);
            }
            *(float2*)&C[(size_t)row0 * LD + col]       = v0;
            *(float2*)&C[(size_t)(row0 + 8) * LD + col] = v1;
        }
    }
}

// ---------------- final concat: out[t] = [h[head], r, h[tail]] --------------
__global__ void final_gather(const float* __restrict__ h,
                             const float* __restrict__ r,
                             const int* __restrict__ head,
                             const int* __restrict__ tail,
                             float* __restrict__ out) {
    const int t = blockIdx.x;
    const int b = t / MT;
    const float4* hh = (const float4*)(h + ((size_t)b * MC + head[t]) * E_);
    const float4* ht = (const float4*)(h + ((size_t)b * MC + tail[t]) * E_);
    const float4* rr = (const float4*)(r + (size_t)t * E_);
    float4* o = (float4*)(out + (size_t)t * 3 * E_);
    const int i = threadIdx.x;     // 0..127
    o[i]       = hh[i];
    o[128 + i] = rr[i];
    o[256 + i] = ht[i];
}

// ---------------- host launch ------------------------------------------------
extern "C" void kernel_launch(void* const* d_in, const int* in_sizes, int n_in,
                              void* d_out, int out_size) {
    const float* concept_table  = (const float*)d_in[0];
    const float* relation_table = (const float*)d_in[1];
    const float* W_s            = (const float*)d_in[2];
    const float* W_n            = (const float*)d_in[3];
    const float* W_r            = (const float*)d_in[4];
    const int*   concept_ids    = (const int*)d_in[5];
    const int*   relation_ids   = (const int*)d_in[6];
    const int*   head_idx       = (const int*)d_in[7];
    const int*   tail_idx       = (const int*)d_in[8];
    const int*   labels         = (const int*)d_in[9];
    float*       out            = (float*)d_out;

    float *h, *h2, *r, *r2, *upd, *cnt;
    cudaGetSymbolAddress((void**)&h,   g_h);
    cudaGetSymbolAddress((void**)&h2,  g_h2);
    cudaGetSymbolAddress((void**)&r,   g_r);
    cudaGetSymbolAddress((void**)&r2,  g_r2);
    cudaGetSymbolAddress((void**)&upd, g_upd);
    cudaGetSymbolAddress((void**)&cnt, g_cnt);

    gather_rows<<<NROW_H, 128>>>(concept_table, concept_ids, h);
    gather_rows<<<NROW_R, 128>>>(relation_table, relation_ids, r);

    float* hc = h;  float* hn = h2;
    float* rc = r;  float* rn = r2;

    for (int l = 0; l < NHOP; ++l) {
        cudaMemsetAsync(upd, 0, sizeof(float) * (size_t)NROW_H * E_);
        cudaMemsetAsync(cnt, 0, sizeof(float) * (size_t)NROW_H);

        scatter_upd<<<NROW_R, 128>>>(head_idx, tail_idx, labels, hc, rc, upd, cnt);
        scale_upd<<<NROW_H, 128>>>(upd, cnt);

        const float* Ws = W_s + (size_t)l * E_ * E_;
        const float* Wn = W_n + (size_t)l * E_ * E_;
        const float* Wr = W_r + (size_t)l * E_ * E_;

        dim3 gh(E_ / 128, NROW_H / 128);           // (4, 256)
        gemm_tf32<2, true><<<gh, 128>>>(hc, Ws, upd, Wn, hn);

        dim3 gr(E_ / 128, NROW_R / 128);           // (4, 512)
        gemm_tf32<1, false><<<gr, 128>>>(rc, Wr, rc, Wr, rn);

        float* tmp;
        tmp = hc; hc = hn; hn = tmp;
        tmp = rc; rc = rn; rn = tmp;
    }

    final_gather<<<NROW_R, 128>>>(hc, rc, head_idx, tail_idx, out);
}